// round 1
// baseline (speedup 1.0000x reference)
#include <cuda_runtime.h>
#include <math.h>

// Problem constants
static constexpr int Bn = 8;
static constexpr int Cn = 128;
static constexpr int On = 256;
static constexpr int Hn = 96;
static constexpr int Wn = 96;
static constexpr int HWn = Hn * Wn;        // 9216
static constexpr int KKn = 9;
static constexpr int CKn = Cn * KKn;       // 1152
static constexpr int NCH = 27;             // 18 offset + 9 mask channels
static constexpr int TP = 32;              // pixels per block in main kernel

// Scratch (no allocations allowed)
__device__ float g_offmask[Bn * NCH * HWn];   // [b][27][HW]: ch<18 offset, 18..26 sigmoid(mask)
__device__ float g_wT[CKn * On];              // [ck][o]

// ---------------------------------------------------------------------------
// Kernel 0: transpose main-conv weight [O][C*9] -> [C*9][O] for coalesced reads
// ---------------------------------------------------------------------------
__global__ void transpose_w(const float* __restrict__ w) {
    int i = blockIdx.x * 256 + threadIdx.x;
    if (i < CKn * On) {
        int ck = i / On, o = i % On;
        g_wT[i] = w[o * CKn + ck];
    }
}

// ---------------------------------------------------------------------------
// Kernel 1: offset + mask 3x3 conv (27 output channels), direct, fp32
// One thread per output pixel, weights staged in shared memory (padded to 12).
// ---------------------------------------------------------------------------
static constexpr int WS1_FLOATS = NCH * Cn * 12;           // 41472
static constexpr int WS1_BYTES  = WS1_FLOATS * 4;          // 165888

__global__ void __launch_bounds__(256) offmask_kernel(
    const float* __restrict__ x,
    const float* __restrict__ off_w, const float* __restrict__ off_b,
    const float* __restrict__ msk_w, const float* __restrict__ msk_b)
{
    extern __shared__ float ws[];  // [27][128][12] (taps 0..8 valid, 9..11 zero)
    int tid = threadIdx.x;
    for (int i = tid; i < WS1_FLOATS; i += 256) {
        int tap = i % 12;
        int c   = (i / 12) % Cn;
        int ch  = i / (12 * Cn);
        float v = 0.0f;
        if (tap < 9)
            v = (ch < 18) ? off_w[(ch * Cn + c) * 9 + tap]
                          : msk_w[((ch - 18) * Cn + c) * 9 + tap];
        ws[i] = v;
    }
    __syncthreads();

    int g = blockIdx.x * 256 + tid;       // 0 .. B*HW-1 (exactly 288 blocks)
    int b   = g / HWn;
    int pix = g % HWn;
    int oh  = pix / Wn;
    int owp = pix % Wn;

    int  offs[9];
    bool valt[9];
#pragma unroll
    for (int kh = 0; kh < 3; kh++)
#pragma unroll
        for (int kw = 0; kw < 3; kw++) {
            int y  = oh - 1 + kh;
            int xx = owp - 1 + kw;
            bool v = (y >= 0 && y < Hn && xx >= 0 && xx < Wn);
            valt[kh * 3 + kw] = v;
            offs[kh * 3 + kw] = v ? (y * Wn + xx) : 0;
        }

    float acc[NCH];
#pragma unroll
    for (int ch = 0; ch < NCH; ch++)
        acc[ch] = (ch < 18) ? off_b[ch] : msk_b[ch - 18];

    const float* xb = x + (size_t)b * Cn * HWn;
    for (int c = 0; c < Cn; c++) {
        float xv[9];
        const float* xc = xb + c * HWn;
#pragma unroll
        for (int j = 0; j < 9; j++)
            xv[j] = valt[j] ? xc[offs[j]] : 0.0f;
#pragma unroll
        for (int ch = 0; ch < NCH; ch++) {
            const float4* wp = (const float4*)&ws[(ch * Cn + c) * 12];
            float4 wa = wp[0];
            float4 wb = wp[1];
            float  w8 = ws[(ch * Cn + c) * 12 + 8];
            acc[ch] += xv[0] * wa.x + xv[1] * wa.y + xv[2] * wa.z + xv[3] * wa.w
                     + xv[4] * wb.x + xv[5] * wb.y + xv[6] * wb.z + xv[7] * wb.w
                     + xv[8] * w8;
        }
    }

    float* dst = g_offmask + (size_t)b * NCH * HWn + pix;
#pragma unroll
    for (int ch = 0; ch < NCH; ch++) {
        float v = acc[ch];
        if (ch >= 18) v = 1.0f / (1.0f + expf(-v));   // sigmoid for mask
        dst[ch * HWn] = v;
    }
}

// ---------------------------------------------------------------------------
// Kernel 2: bilinear sampling + main GEMM, fused per 32-pixel tile
// ---------------------------------------------------------------------------
static constexpr int META_N   = TP * KKn;                       // 288
static constexpr int SM2_FLOATS = CKn * TP + META_N * 8;        // samples + meta
static constexpr int SM2_BYTES  = SM2_FLOATS * 4;               // 156672

__global__ void __launch_bounds__(256) deform_main(
    const float* __restrict__ x,
    const float* __restrict__ bias,
    float* __restrict__ out)
{
    extern __shared__ float sm[];
    float* s    = sm;                    // [CK][TP]
    float* mw00 = sm + CKn * TP;         // [288] each
    float* mw01 = mw00 + META_N;
    float* mw10 = mw01 + META_N;
    float* mw11 = mw10 + META_N;
    int*   mo00 = (int*)(mw11 + META_N);
    int*   mo01 = mo00 + META_N;
    int*   mo10 = mo01 + META_N;
    int*   mo11 = mo10 + META_N;

    int blk = blockIdx.x;                // b*H*3 blocks
    int b   = blk / (Hn * 3);
    int r   = blk % (Hn * 3);
    int oh  = r / 3;
    int ow0 = (r % 3) * TP;
    int tid = threadIdx.x;

    // Phase 0: sampling metadata (corner offsets + mask-folded bilinear weights)
    const float* om = g_offmask + (size_t)b * NCH * HWn;
    for (int i = tid; i < META_N; i += 256) {
        int p = i / KKn;
        int k = i % KKn;
        int pix = oh * Wn + ow0 + p;
        float offy = om[(2 * k) * HWn + pix];
        float offx = om[(2 * k + 1) * HWn + pix];
        float m    = om[(18 + k) * HWn + pix];
        float py = (float)(oh - 1 + k / 3) + offy;
        float px = (float)(ow0 + p - 1 + k % 3) + offx;
        float y0f = floorf(py), x0f = floorf(px);
        int y0 = (int)y0f, x0 = (int)x0f;
        int y1 = y0 + 1,  x1 = x0 + 1;
        float wy1 = py - y0f, wy0 = 1.0f - wy1;
        float wx1 = px - x0f, wx0 = 1.0f - wx1;
        bool vy0 = (y0 >= 0 && y0 < Hn), vy1 = (y1 >= 0 && y1 < Hn);
        bool vx0 = (x0 >= 0 && x0 < Wn), vx1 = (x1 >= 0 && x1 < Wn);
        int cy0 = min(max(y0, 0), Hn - 1), cy1 = min(max(y1, 0), Hn - 1);
        int cx0 = min(max(x0, 0), Wn - 1), cx1 = min(max(x1, 0), Wn - 1);
        mw00[i] = wy0 * wx0 * m * ((vy0 && vx0) ? 1.0f : 0.0f);
        mw01[i] = wy0 * wx1 * m * ((vy0 && vx1) ? 1.0f : 0.0f);
        mw10[i] = wy1 * wx0 * m * ((vy1 && vx0) ? 1.0f : 0.0f);
        mw11[i] = wy1 * wx1 * m * ((vy1 && vx1) ? 1.0f : 0.0f);
        mo00[i] = cy0 * Wn + cx0;
        mo01[i] = cy0 * Wn + cx1;
        mo10[i] = cy1 * Wn + cx0;
        mo11[i] = cy1 * Wn + cx1;
    }
    __syncthreads();

    // Phase 1: gather samples into smem, s[ck][p], mask pre-folded
    {
        int lane = tid & 31;
        int grp  = tid >> 5;
        const float* xb = x + (size_t)b * Cn * HWn;
        for (int ck = grp; ck < CKn; ck += 8) {
            int c = ck / 9, k = ck % 9;
            int mi = lane * KKn + k;
            const float* xc = xb + c * HWn;
            float v = mw00[mi] * xc[mo00[mi]] + mw01[mi] * xc[mo01[mi]]
                    + mw10[mi] * xc[mo10[mi]] + mw11[mi] * xc[mo11[mi]];
            s[ck * TP + lane] = v;
        }
    }
    __syncthreads();

    // Phase 2: GEMM — thread = output channel o, 32 fp32 accumulators
    {
        int o = tid;
        float acc[TP];
#pragma unroll
        for (int p = 0; p < TP; p++) acc[p] = 0.0f;

        const float* wv = g_wT + o;
        const float4* s4 = (const float4*)s;

        // software-pipeline the weight loads (2 ahead, L2 latency ~250cyc)
        float w0 = wv[0];
        float w1 = wv[On];
        for (int ck = 0; ck < CKn; ck++) {
            float wn = (ck + 2 < CKn) ? wv[(ck + 2) * On] : 0.0f;
            const float4* row = s4 + ck * (TP / 4);
#pragma unroll
            for (int q = 0; q < TP / 4; q++) {
                float4 sv = row[q];
                acc[4 * q + 0] += sv.x * w0;
                acc[4 * q + 1] += sv.y * w0;
                acc[4 * q + 2] += sv.z * w0;
                acc[4 * q + 3] += sv.w * w0;
            }
            w0 = w1;
            w1 = wn;
        }

        float bo = bias[o];
        float* dst = out + (((size_t)b * On + o) * Hn + oh) * Wn + ow0;
#pragma unroll
        for (int p = 0; p < TP; p++) dst[p] = acc[p] + bo;
    }
}

// ---------------------------------------------------------------------------
// Launch
// ---------------------------------------------------------------------------
extern "C" void kernel_launch(void* const* d_in, const int* in_sizes, int n_in,
                              void* d_out, int out_size)
{
    const float* x        = (const float*)d_in[0];
    const float* offset_w = (const float*)d_in[1];
    const float* offset_b = (const float*)d_in[2];
    const float* mask_w   = (const float*)d_in[3];
    const float* mask_b   = (const float*)d_in[4];
    const float* weight   = (const float*)d_in[5];
    const float* bias     = (const float*)d_in[6];
    float* out = (float*)d_out;

    cudaFuncSetAttribute(offmask_kernel,
                         cudaFuncAttributeMaxDynamicSharedMemorySize, WS1_BYTES);
    cudaFuncSetAttribute(deform_main,
                         cudaFuncAttributeMaxDynamicSharedMemorySize, SM2_BYTES);

    transpose_w<<<(CKn * On + 255) / 256, 256>>>(weight);
    offmask_kernel<<<(Bn * HWn) / 256, 256, WS1_BYTES>>>(
        x, offset_w, offset_b, mask_w, mask_b);
    deform_main<<<Bn * Hn * 3, 256, SM2_BYTES>>>(x, bias, out);
}

// round 5
// speedup vs baseline: 3.8215x; 3.8215x over previous
#include <cuda_runtime.h>
#include <cuda_bf16.h>
#include <math.h>
#include <cstdint>

// Problem constants
static constexpr int Bn = 8;
static constexpr int Cn = 128;
static constexpr int On = 256;
static constexpr int Hn = 96;
static constexpr int Wn = 96;
static constexpr int HWn = Hn * Wn;        // 9216
static constexpr int KKn = 9;
static constexpr int CKn = Cn * KKn;       // 1152
static constexpr int NCH = 27;
static constexpr int KP  = 2 * CKn;        // 2304: A stored as [Ah | Al]
static constexpr int KP3 = 3 * CKn;        // 3456: logical GEMM K (A3=[Ah|Al|Ah], B3=[Bh|Bh|Bl])
static constexpr int MTOT = Bn * HWn;      // 73728
static constexpr int BM = 128, BN = 128, BK = 32;
static constexpr int NST = KP3 / BK;       // 108

// Scratch
__device__ float         g_offmask[Bn * NCH * HWn];
__device__ __nv_bfloat16 g_A2[(size_t)MTOT * KP];     // [Ah | Al] per row
__device__ __nv_bfloat16 g_B2[(size_t)On * KP3];      // [Bh | Bh | Bl] per row

// ---------------------------------------------------------------------------
// PTX helpers (base sm_103-safe: cp.async + ldmatrix + mma.sync)
// ---------------------------------------------------------------------------
__device__ __forceinline__ uint32_t smem_u32(const void* p) {
    uint32_t a;
    asm("{ .reg .u64 t; cvta.to.shared.u64 t, %1; cvt.u32.u64 %0, t; }"
        : "=r"(a) : "l"(p));
    return a;
}
__device__ __forceinline__ void cp_async16(uint32_t dst, const void* src) {
    asm volatile("cp.async.cg.shared.global [%0], [%1], 16;"
                 :: "r"(dst), "l"(src) : "memory");
}
#define CP_COMMIT() asm volatile("cp.async.commit_group;" ::: "memory")
#define CP_WAIT1()  asm volatile("cp.async.wait_group 1;" ::: "memory")
#define CP_WAIT0()  asm volatile("cp.async.wait_group 0;" ::: "memory")

__device__ __forceinline__ void ldmx4(uint32_t& r0, uint32_t& r1,
                                      uint32_t& r2, uint32_t& r3, uint32_t addr) {
    asm volatile("ldmatrix.sync.aligned.m8n8.x4.shared.b16 {%0,%1,%2,%3}, [%4];"
                 : "=r"(r0), "=r"(r1), "=r"(r2), "=r"(r3) : "r"(addr));
}
__device__ __forceinline__ void mma_bf16(float* c, const uint32_t* a,
                                         uint32_t b0, uint32_t b1) {
    asm volatile(
        "mma.sync.aligned.m16n8k16.row.col.f32.bf16.bf16.f32 "
        "{%0,%1,%2,%3}, {%4,%5,%6,%7}, {%8,%9}, {%0,%1,%2,%3};"
        : "+f"(c[0]), "+f"(c[1]), "+f"(c[2]), "+f"(c[3])
        : "r"(a[0]), "r"(a[1]), "r"(a[2]), "r"(a[3]), "r"(b0), "r"(b1));
}

// ---------------------------------------------------------------------------
// Kernel: weight -> bf16 3-term layout [Bh | Bh | Bl], [O][KP3]
// ---------------------------------------------------------------------------
__global__ void prep_w(const float* __restrict__ w) {
    int i = blockIdx.x * 256 + threadIdx.x;
    if (i < On * CKn) {
        int o = i / CKn, ck = i % CKn;
        float v = w[i];
        __nv_bfloat16 hi = __float2bfloat16(v);
        __nv_bfloat16 lo = __float2bfloat16(v - __bfloat162float(hi));
        __nv_bfloat16* row = g_B2 + (size_t)o * KP3;
        row[ck]           = hi;   // pairs with Ah
        row[CKn + ck]     = hi;   // pairs with Al
        row[2 * CKn + ck] = lo;   // pairs with Ah
    }
}

// ---------------------------------------------------------------------------
// Kernel: offset + mask 3x3 conv (27 channels), fp32 direct (verified R1)
// ---------------------------------------------------------------------------
static constexpr int WS1_FLOATS = NCH * Cn * 12;
static constexpr int WS1_BYTES  = WS1_FLOATS * 4;

__global__ void __launch_bounds__(256) offmask_kernel(
    const float* __restrict__ x,
    const float* __restrict__ off_w, const float* __restrict__ off_b,
    const float* __restrict__ msk_w, const float* __restrict__ msk_b)
{
    extern __shared__ float ws[];
    int tid = threadIdx.x;
    for (int i = tid; i < WS1_FLOATS; i += 256) {
        int tap = i % 12;
        int c   = (i / 12) % Cn;
        int ch  = i / (12 * Cn);
        float v = 0.0f;
        if (tap < 9)
            v = (ch < 18) ? off_w[(ch * Cn + c) * 9 + tap]
                          : msk_w[((ch - 18) * Cn + c) * 9 + tap];
        ws[i] = v;
    }
    __syncthreads();

    int g = blockIdx.x * 256 + tid;
    int b   = g / HWn;
    int pix = g % HWn;
    int oh  = pix / Wn;
    int owp = pix % Wn;

    int  offs[9];
    bool valt[9];
#pragma unroll
    for (int kh = 0; kh < 3; kh++)
#pragma unroll
        for (int kw = 0; kw < 3; kw++) {
            int y  = oh - 1 + kh;
            int xx = owp - 1 + kw;
            bool v = (y >= 0 && y < Hn && xx >= 0 && xx < Wn);
            valt[kh * 3 + kw] = v;
            offs[kh * 3 + kw] = v ? (y * Wn + xx) : 0;
        }

    float acc[NCH];
#pragma unroll
    for (int ch = 0; ch < NCH; ch++)
        acc[ch] = (ch < 18) ? off_b[ch] : msk_b[ch - 18];

    const float* xb = x + (size_t)b * Cn * HWn;
    for (int c = 0; c < Cn; c++) {
        float xv[9];
        const float* xc = xb + c * HWn;
#pragma unroll
        for (int j = 0; j < 9; j++)
            xv[j] = valt[j] ? xc[offs[j]] : 0.0f;
#pragma unroll
        for (int ch = 0; ch < NCH; ch++) {
            const float4* wp = (const float4*)&ws[(ch * Cn + c) * 12];
            float4 wa = wp[0];
            float4 wb = wp[1];
            float  w8 = ws[(ch * Cn + c) * 12 + 8];
            acc[ch] += xv[0] * wa.x + xv[1] * wa.y + xv[2] * wa.z + xv[3] * wa.w
                     + xv[4] * wb.x + xv[5] * wb.y + xv[6] * wb.z + xv[7] * wb.w
                     + xv[8] * w8;
        }
    }

    float* dst = g_offmask + (size_t)b * NCH * HWn + pix;
#pragma unroll
    for (int ch = 0; ch < NCH; ch++) {
        float v = acc[ch];
        if (ch >= 18) v = 1.0f / (1.0f + expf(-v));
        dst[ch * HWn] = v;
    }
}

// ---------------------------------------------------------------------------
// Kernel: bilinear gather -> A2 [M][KP] bf16 [Ah | Al], mask folded in
// ---------------------------------------------------------------------------
__global__ void __launch_bounds__(256) gather_kernel(const float* __restrict__ x)
{
    __shared__ float mw00[288], mw01[288], mw10[288], mw11[288];
    __shared__ int   mo00[288], mo01[288], mo10[288], mo11[288];

    int blk = blockIdx.x;
    int b   = blk / (Hn * 3);
    int r   = blk % (Hn * 3);
    int oh  = r / 3;
    int ow0 = (r % 3) * 32;
    int tid = threadIdx.x;

    const float* om = g_offmask + (size_t)b * NCH * HWn;
    for (int i = tid; i < 288; i += 256) {
        int p = i / KKn;
        int k = i % KKn;
        int pix = oh * Wn + ow0 + p;
        float offy = om[(2 * k) * HWn + pix];
        float offx = om[(2 * k + 1) * HWn + pix];
        float m    = om[(18 + k) * HWn + pix];
        float py = (float)(oh - 1 + k / 3) + offy;
        float px = (float)(ow0 + p - 1 + k % 3) + offx;
        float y0f = floorf(py), x0f = floorf(px);
        int y0 = (int)y0f, x0 = (int)x0f;
        int y1 = y0 + 1,  x1 = x0 + 1;
        float wy1 = py - y0f, wy0 = 1.0f - wy1;
        float wx1 = px - x0f, wx0 = 1.0f - wx1;
        bool vy0 = (y0 >= 0 && y0 < Hn), vy1 = (y1 >= 0 && y1 < Hn);
        bool vx0 = (x0 >= 0 && x0 < Wn), vx1 = (x1 >= 0 && x1 < Wn);
        int cy0 = min(max(y0, 0), Hn - 1), cy1 = min(max(y1, 0), Hn - 1);
        int cx0 = min(max(x0, 0), Wn - 1), cx1 = min(max(x1, 0), Wn - 1);
        mw00[i] = wy0 * wx0 * m * ((vy0 && vx0) ? 1.0f : 0.0f);
        mw01[i] = wy0 * wx1 * m * ((vy0 && vx1) ? 1.0f : 0.0f);
        mw10[i] = wy1 * wx0 * m * ((vy1 && vx0) ? 1.0f : 0.0f);
        mw11[i] = wy1 * wx1 * m * ((vy1 && vx1) ? 1.0f : 0.0f);
        mo00[i] = cy0 * Wn + cx0;
        mo01[i] = cy0 * Wn + cx1;
        mo10[i] = cy1 * Wn + cx0;
        mo11[i] = cy1 * Wn + cx1;
    }
    __syncthreads();

    const float* xb = x + (size_t)b * Cn * HWn;
    size_t arow0 = ((size_t)b * HWn + oh * Wn + ow0) * KP;

#pragma unroll
    for (int i = 0; i < 5; i++) {
        int ck = tid + i * 256;
        if (ck < CKn) {
            int c = ck / 9, k = ck - c * 9;
            const float* xc = xb + c * HWn;
            __nv_bfloat16* dst = g_A2 + arow0 + ck;
#pragma unroll 4
            for (int p = 0; p < 32; p++) {
                int mi = p * 9 + k;
                float v = mw00[mi] * xc[mo00[mi]] + mw01[mi] * xc[mo01[mi]]
                        + mw10[mi] * xc[mo10[mi]] + mw11[mi] * xc[mo11[mi]];
                __nv_bfloat16 hi = __float2bfloat16(v);
                __nv_bfloat16 lo = __float2bfloat16(v - __bfloat162float(hi));
                dst[(size_t)p * KP]       = hi;
                dst[(size_t)p * KP + CKn] = lo;
            }
        }
    }
}

// ---------------------------------------------------------------------------
// Kernel: bf16 HMMA GEMM (mma.sync m16n8k16), CTA 128x128, BK=32, 2-stage
// cp.async pipeline. K' = 3456 (3-term error-compensated split).
// A segment 3 aliases segment 1 (source offset remap in loader).
// ---------------------------------------------------------------------------
static constexpr int APITCH = 40;                 // bf16 per smem row
static constexpr int ABYTES = BM * APITCH * 2;    // 10240
static constexpr int BUFB   = 2 * ABYTES;         // A+B per stage: 20480

__global__ void __launch_bounds__(256, 2) gemm_kernel(
    const float* __restrict__ bias, float* __restrict__ out)
{
    __shared__ __align__(16) char sm[2 * BUFB];   // 40 KB
    uint32_t sb = smem_u32(sm);
    int tid  = threadIdx.x;
    int wid  = tid >> 5;
    int lane = tid & 31;
    int wm = wid & 3;          // M warp 0..3
    int wn = wid >> 2;         // N warp 0..1

    int row0 = blockIdx.x * BM;
    int col0 = blockIdx.y * BN;

    int c0 = tid, c1 = tid + 256;

    auto load_stage = [&](int s) {
        int kc  = s * BK;
        int akc = (kc < KP) ? kc : kc - KP;   // A: third segment re-reads Ah
        uint32_t dst = sb + (s & 1) * BUFB;
        // A
        {
            int r = c0 >> 2, u = c0 & 3;
            cp_async16(dst + r * 80 + u * 16,
                       g_A2 + (size_t)(row0 + r) * KP + akc + u * 8);
            r = c1 >> 2; u = c1 & 3;
            cp_async16(dst + r * 80 + u * 16,
                       g_A2 + (size_t)(row0 + r) * KP + akc + u * 8);
        }
        // B
        {
            uint32_t dstb = dst + ABYTES;
            int r = c0 >> 2, u = c0 & 3;
            cp_async16(dstb + r * 80 + u * 16,
                       g_B2 + (size_t)(col0 + r) * KP3 + kc + u * 8);
            r = c1 >> 2; u = c1 & 3;
            cp_async16(dstb + r * 80 + u * 16,
                       g_B2 + (size_t)(col0 + r) * KP3 + kc + u * 8);
        }
        CP_COMMIT();
    };

    float acc[2][8][4];
#pragma unroll
    for (int mt = 0; mt < 2; mt++)
#pragma unroll
        for (int nt = 0; nt < 8; nt++)
#pragma unroll
            for (int e = 0; e < 4; e++) acc[mt][nt][e] = 0.0f;

    load_stage(0);

    int lrow = lane & 15;
    int lcol = (lane >> 4) * 8;

    for (int s = 0; s < NST; s++) {
        if (s + 1 < NST) { load_stage(s + 1); CP_WAIT1(); }
        else             { CP_WAIT0(); }
        __syncthreads();

        uint32_t bufA = sb + (s & 1) * BUFB;
        uint32_t bufB = bufA + ABYTES;

#pragma unroll
        for (int kk = 0; kk < 2; kk++) {
            uint32_t a[2][4];
#pragma unroll
            for (int mt = 0; mt < 2; mt++) {
                int row = wm * 32 + mt * 16 + lrow;
                int col = kk * 16 + lcol;
                ldmx4(a[mt][0], a[mt][1], a[mt][2], a[mt][3],
                      bufA + row * 80 + col * 2);
            }
#pragma unroll
            for (int ntp = 0; ntp < 4; ntp++) {
                int row = wn * 64 + ntp * 16 + lrow;
                int col = kk * 16 + lcol;
                uint32_t b0, b1, b2, b3;
                ldmx4(b0, b1, b2, b3, bufB + row * 80 + col * 2);
#pragma unroll
                for (int mt = 0; mt < 2; mt++) {
                    mma_bf16(acc[mt][2 * ntp],     a[mt], b0, b2);
                    mma_bf16(acc[mt][2 * ntp + 1], a[mt], b1, b3);
                }
            }
        }
        __syncthreads();
    }

    // Epilogue: direct stores (validated R2 mapping)
    int quad = lane >> 2;
    int tq   = lane & 3;
#pragma unroll
    for (int mt = 0; mt < 2; mt++) {
        int m = row0 + wm * 32 + mt * 16 + quad;
        int b   = m / HWn;
        int pix = m % HWn;
        float* ob = out + (size_t)b * On * HWn;
#pragma unroll
        for (int nt = 0; nt < 8; nt++) {
            int o = col0 + wn * 64 + nt * 8 + tq * 2;
            float b0v = __ldg(bias + o);
            float b1v = __ldg(bias + o + 1);
            float* p0 = ob + (size_t)o * HWn + pix;
            float* p1 = ob + (size_t)(o + 1) * HWn + pix;
            p0[0] = acc[mt][nt][0] + b0v;
            p1[0] = acc[mt][nt][1] + b1v;
            p0[8] = acc[mt][nt][2] + b0v;
            p1[8] = acc[mt][nt][3] + b1v;
        }
    }
}

// ---------------------------------------------------------------------------
// Launch
// ---------------------------------------------------------------------------
extern "C" void kernel_launch(void* const* d_in, const int* in_sizes, int n_in,
                              void* d_out, int out_size)
{
    const float* x        = (const float*)d_in[0];
    const float* offset_w = (const float*)d_in[1];
    const float* offset_b = (const float*)d_in[2];
    const float* mask_w   = (const float*)d_in[3];
    const float* mask_b   = (const float*)d_in[4];
    const float* weight   = (const float*)d_in[5];
    const float* bias     = (const float*)d_in[6];
    float* out = (float*)d_out;

    cudaFuncSetAttribute(offmask_kernel,
                         cudaFuncAttributeMaxDynamicSharedMemorySize, WS1_BYTES);

    prep_w<<<(On * CKn + 255) / 256, 256>>>(weight);
    offmask_kernel<<<(Bn * HWn) / 256, 256, WS1_BYTES>>>(
        x, offset_w, offset_b, mask_w, mask_b);
    gather_kernel<<<Bn * Hn * 3, 256>>>(x);
    dim3 grid(MTOT / BM, On / BN);
    gemm_kernel<<<grid, 256>>>(bias, out);
}

// round 8
// speedup vs baseline: 3.8663x; 1.0117x over previous
#include <cuda_runtime.h>
#include <cuda_bf16.h>
#include <math.h>
#include <cstdint>

// Problem constants
static constexpr int Bn = 8;
static constexpr int Cn = 128;
static constexpr int On = 256;
static constexpr int Hn = 96;
static constexpr int Wn = 96;
static constexpr int HWn = Hn * Wn;        // 9216
static constexpr int KKn = 9;
static constexpr int CKn = Cn * KKn;       // 1152
static constexpr int NCH = 27;
static constexpr int KP  = 2 * CKn;        // 2304: A stored as [Ah | Al]
static constexpr int KP3 = 3 * CKn;        // 3456: logical GEMM K
static constexpr int MTOT = Bn * HWn;      // 73728
static constexpr int BM = 128, BN = 128, BK = 32;
static constexpr int NST = KP3 / BK;       // 108

// Scratch
__device__ float         g_offmask[Bn * NCH * HWn];
__device__ __nv_bfloat16 g_A2[(size_t)MTOT * KP];     // [Ah | Al] per row
__device__ __nv_bfloat16 g_B2[(size_t)On * KP3];      // [Bh | Bh | Bl] per row

// ---------------------------------------------------------------------------
// PTX helpers
// ---------------------------------------------------------------------------
__device__ __forceinline__ uint32_t smem_u32(const void* p) {
    uint32_t a;
    asm("{ .reg .u64 t; cvta.to.shared.u64 t, %1; cvt.u32.u64 %0, t; }"
        : "=r"(a) : "l"(p));
    return a;
}
__device__ __forceinline__ void cp_async16(uint32_t dst, const void* src) {
    asm volatile("cp.async.cg.shared.global [%0], [%1], 16;"
                 :: "r"(dst), "l"(src) : "memory");
}
#define CP_COMMIT() asm volatile("cp.async.commit_group;" ::: "memory")
#define CP_WAIT2()  asm volatile("cp.async.wait_group 2;" ::: "memory")

__device__ __forceinline__ void ldmx4(uint32_t& r0, uint32_t& r1,
                                      uint32_t& r2, uint32_t& r3, uint32_t addr) {
    asm volatile("ldmatrix.sync.aligned.m8n8.x4.shared.b16 {%0,%1,%2,%3}, [%4];"
                 : "=r"(r0), "=r"(r1), "=r"(r2), "=r"(r3) : "r"(addr));
}
__device__ __forceinline__ void mma_bf16(float* c, const uint32_t* a,
                                         uint32_t b0, uint32_t b1) {
    asm volatile(
        "mma.sync.aligned.m16n8k16.row.col.f32.bf16.bf16.f32 "
        "{%0,%1,%2,%3}, {%4,%5,%6,%7}, {%8,%9}, {%0,%1,%2,%3};"
        : "+f"(c[0]), "+f"(c[1]), "+f"(c[2]), "+f"(c[3])
        : "r"(a[0]), "r"(a[1]), "r"(a[2]), "r"(a[3]), "r"(b0), "r"(b1));
}

// ---------------------------------------------------------------------------
// Kernel: weight -> bf16 3-term layout [Bh | Bh | Bl], [O][KP3]
// ---------------------------------------------------------------------------
__global__ void prep_w(const float* __restrict__ w) {
    int i = blockIdx.x * 256 + threadIdx.x;
    if (i < On * CKn) {
        int o = i / CKn, ck = i % CKn;
        float v = w[i];
        __nv_bfloat16 hi = __float2bfloat16(v);
        __nv_bfloat16 lo = __float2bfloat16(v - __bfloat162float(hi));
        __nv_bfloat16* row = g_B2 + (size_t)o * KP3;
        row[ck]           = hi;
        row[CKn + ck]     = hi;
        row[2 * CKn + ck] = lo;
    }
}

// ---------------------------------------------------------------------------
// Kernel: offset + mask 3x3 conv (27 channels), fp32 direct (verified)
// ---------------------------------------------------------------------------
static constexpr int WS1_FLOATS = NCH * Cn * 12;
static constexpr int WS1_BYTES  = WS1_FLOATS * 4;

__global__ void __launch_bounds__(256) offmask_kernel(
    const float* __restrict__ x,
    const float* __restrict__ off_w, const float* __restrict__ off_b,
    const float* __restrict__ msk_w, const float* __restrict__ msk_b)
{
    extern __shared__ float ws[];
    int tid = threadIdx.x;
    for (int i = tid; i < WS1_FLOATS; i += 256) {
        int tap = i % 12;
        int c   = (i / 12) % Cn;
        int ch  = i / (12 * Cn);
        float v = 0.0f;
        if (tap < 9)
            v = (ch < 18) ? off_w[(ch * Cn + c) * 9 + tap]
                          : msk_w[((ch - 18) * Cn + c) * 9 + tap];
        ws[i] = v;
    }
    __syncthreads();

    int g = blockIdx.x * 256 + tid;
    int b   = g / HWn;
    int pix = g % HWn;
    int oh  = pix / Wn;
    int owp = pix % Wn;

    int  offs[9];
    bool valt[9];
#pragma unroll
    for (int kh = 0; kh < 3; kh++)
#pragma unroll
        for (int kw = 0; kw < 3; kw++) {
            int y  = oh - 1 + kh;
            int xx = owp - 1 + kw;
            bool v = (y >= 0 && y < Hn && xx >= 0 && xx < Wn);
            valt[kh * 3 + kw] = v;
            offs[kh * 3 + kw] = v ? (y * Wn + xx) : 0;
        }

    float acc[NCH];
#pragma unroll
    for (int ch = 0; ch < NCH; ch++)
        acc[ch] = (ch < 18) ? off_b[ch] : msk_b[ch - 18];

    const float* xb = x + (size_t)b * Cn * HWn;
    for (int c = 0; c < Cn; c++) {
        float xv[9];
        const float* xc = xb + c * HWn;
#pragma unroll
        for (int j = 0; j < 9; j++)
            xv[j] = valt[j] ? xc[offs[j]] : 0.0f;
#pragma unroll
        for (int ch = 0; ch < NCH; ch++) {
            const float4* wp = (const float4*)&ws[(ch * Cn + c) * 12];
            float4 wa = wp[0];
            float4 wb = wp[1];
            float  w8 = ws[(ch * Cn + c) * 12 + 8];
            acc[ch] += xv[0] * wa.x + xv[1] * wa.y + xv[2] * wa.z + xv[3] * wa.w
                     + xv[4] * wb.x + xv[5] * wb.y + xv[6] * wb.z + xv[7] * wb.w
                     + xv[8] * w8;
        }
    }

    float* dst = g_offmask + (size_t)b * NCH * HWn + pix;
#pragma unroll
    for (int ch = 0; ch < NCH; ch++) {
        float v = acc[ch];
        if (ch >= 18) v = 1.0f / (1.0f + expf(-v));
        dst[ch * HWn] = v;
    }
}

// ---------------------------------------------------------------------------
// Kernel: bilinear gather -> A2 [M][KP] bf16 [Ah | Al], mask folded in
// v2: warp-per-pixel; lane l handles ck = l + 32j -> coalesced stores.
// ---------------------------------------------------------------------------
__global__ void __launch_bounds__(256) gather_kernel(const float* __restrict__ x)
{
    __shared__ float mw00[288], mw01[288], mw10[288], mw11[288];
    __shared__ int   mo00[288], mo01[288], mo10[288], mo11[288];

    int blk = blockIdx.x;
    int b   = blk / (Hn * 3);
    int r   = blk % (Hn * 3);
    int oh  = r / 3;
    int ow0 = (r % 3) * 32;
    int tid = threadIdx.x;
    int wid = tid >> 5;
    int lane = tid & 31;

    const float* om = g_offmask + (size_t)b * NCH * HWn;
    for (int i = tid; i < 288; i += 256) {
        int p = i / KKn;
        int k = i % KKn;
        int pix = oh * Wn + ow0 + p;
        float offy = om[(2 * k) * HWn + pix];
        float offx = om[(2 * k + 1) * HWn + pix];
        float m    = om[(18 + k) * HWn + pix];
        float py = (float)(oh - 1 + k / 3) + offy;
        float px = (float)(ow0 + p - 1 + k % 3) + offx;
        float y0f = floorf(py), x0f = floorf(px);
        int y0 = (int)y0f, x0 = (int)x0f;
        int y1 = y0 + 1,  x1 = x0 + 1;
        float wy1 = py - y0f, wy0 = 1.0f - wy1;
        float wx1 = px - x0f, wx0 = 1.0f - wx1;
        bool vy0 = (y0 >= 0 && y0 < Hn), vy1 = (y1 >= 0 && y1 < Hn);
        bool vx0 = (x0 >= 0 && x0 < Wn), vx1 = (x1 >= 0 && x1 < Wn);
        int cy0 = min(max(y0, 0), Hn - 1), cy1 = min(max(y1, 0), Hn - 1);
        int cx0 = min(max(x0, 0), Wn - 1), cx1 = min(max(x1, 0), Wn - 1);
        mw00[i] = wy0 * wx0 * m * ((vy0 && vx0) ? 1.0f : 0.0f);
        mw01[i] = wy0 * wx1 * m * ((vy0 && vx1) ? 1.0f : 0.0f);
        mw10[i] = wy1 * wx0 * m * ((vy1 && vx0) ? 1.0f : 0.0f);
        mw11[i] = wy1 * wx1 * m * ((vy1 && vx1) ? 1.0f : 0.0f);
        mo00[i] = cy0 * Wn + cx0;
        mo01[i] = cy0 * Wn + cx1;
        mo10[i] = cy1 * Wn + cx0;
        mo11[i] = cy1 * Wn + cx1;
    }
    __syncthreads();

    const float* xb = x + (size_t)b * Cn * HWn;
    size_t arow0 = ((size_t)b * HWn + oh * Wn + ow0) * KP;

    // 4 passes x 8 warps = 32 pixels; lane strides over ck (coalesced stores)
#pragma unroll
    for (int pp = 0; pp < 4; pp++) {
        int p = pp * 8 + wid;
        __nv_bfloat16* dst = g_A2 + arow0 + (size_t)p * KP;
        int mbase = p * 9;
#pragma unroll 4
        for (int j = 0; j < 36; j++) {
            int ck = j * 32 + lane;
            int c = ck / 9, k = ck - c * 9;
            int mi = mbase + k;
            const float* xc = xb + c * HWn;
            float v = mw00[mi] * xc[mo00[mi]] + mw01[mi] * xc[mo01[mi]]
                    + mw10[mi] * xc[mo10[mi]] + mw11[mi] * xc[mo11[mi]];
            __nv_bfloat16 hi = __float2bfloat16(v);
            __nv_bfloat16 lo = __float2bfloat16(v - __bfloat162float(hi));
            dst[ck]       = hi;
            dst[CKn + ck] = lo;
        }
    }
}

// ---------------------------------------------------------------------------
// Kernel: bf16 HMMA GEMM, CTA 128x128, BK=32, 4-stage cp.async pipeline,
// one barrier per K-step. K'=3456 (3-term split, A segment 3 aliases 1).
// ---------------------------------------------------------------------------
static constexpr int APITCH = 40;                 // bf16 per smem row
static constexpr int ABYTES = BM * APITCH * 2;    // 10240
static constexpr int BUFB   = 2 * ABYTES;         // A+B per stage: 20480
static constexpr int GEMM_SMEM = 4 * BUFB;        // 81920

__global__ void __launch_bounds__(256, 2) gemm_kernel(
    const float* __restrict__ bias, float* __restrict__ out)
{
    extern __shared__ __align__(16) char sm[];
    uint32_t sb = smem_u32(sm);
    int tid  = threadIdx.x;
    int wid  = tid >> 5;
    int lane = tid & 31;
    int wm = wid & 3;
    int wn = wid >> 2;

    int row0 = blockIdx.x * BM;
    int col0 = blockIdx.y * BN;

    int c0 = tid, c1 = tid + 256;

    auto load_stage = [&](int s) {
        int kc  = s * BK;
        int akc = (kc < KP) ? kc : kc - KP;   // A third segment re-reads Ah
        uint32_t dst = sb + (s & 3) * BUFB;
        {
            int r = c0 >> 2, u = c0 & 3;
            cp_async16(dst + r * 80 + u * 16,
                       g_A2 + (size_t)(row0 + r) * KP + akc + u * 8);
            r = c1 >> 2; u = c1 & 3;
            cp_async16(dst + r * 80 + u * 16,
                       g_A2 + (size_t)(row0 + r) * KP + akc + u * 8);
        }
        {
            uint32_t dstb = dst + ABYTES;
            int r = c0 >> 2, u = c0 & 3;
            cp_async16(dstb + r * 80 + u * 16,
                       g_B2 + (size_t)(col0 + r) * KP3 + kc + u * 8);
            r = c1 >> 2; u = c1 & 3;
            cp_async16(dstb + r * 80 + u * 16,
                       g_B2 + (size_t)(col0 + r) * KP3 + kc + u * 8);
        }
        CP_COMMIT();
    };

    float acc[2][8][4];
#pragma unroll
    for (int mt = 0; mt < 2; mt++)
#pragma unroll
        for (int nt = 0; nt < 8; nt++)
#pragma unroll
            for (int e = 0; e < 4; e++) acc[mt][nt][e] = 0.0f;

    load_stage(0);
    load_stage(1);
    load_stage(2);

    int lrow = lane & 15;
    int lcol = (lane >> 4) * 8;

    for (int s = 0; s < NST; s++) {
        CP_WAIT2();              // group s complete (<=2 pending)
        __syncthreads();         // all threads done reading buf (s-1)&3
        if (s + 3 < NST) load_stage(s + 3);   // writes buf (s+3)&3 == (s-1)&3

        uint32_t bufA = sb + (s & 3) * BUFB;
        uint32_t bufB = bufA + ABYTES;

#pragma unroll
        for (int kk = 0; kk < 2; kk++) {
            uint32_t a[2][4];
#pragma unroll
            for (int mt = 0; mt < 2; mt++) {
                int row = wm * 32 + mt * 16 + lrow;
                int col = kk * 16 + lcol;
                ldmx4(a[mt][0], a[mt][1], a[mt][2], a[mt][3],
                      bufA + row * 80 + col * 2);
            }
#pragma unroll
            for (int ntp = 0; ntp < 4; ntp++) {
                int row = wn * 64 + ntp * 16 + lrow;
                int col = kk * 16 + lcol;
                uint32_t b0, b1, b2, b3;
                ldmx4(b0, b1, b2, b3, bufB + row * 80 + col * 2);
#pragma unroll
                for (int mt = 0; mt < 2; mt++) {
                    mma_bf16(acc[mt][2 * ntp],     a[mt], b0, b2);
                    mma_bf16(acc[mt][2 * ntp + 1], a[mt], b1, b3);
                }
            }
        }
    }

    // Epilogue
    int quad = lane >> 2;
    int tq   = lane & 3;
#pragma unroll
    for (int mt = 0; mt < 2; mt++) {
        int m = row0 + wm * 32 + mt * 16 + quad;
        int b   = m / HWn;
        int pix = m % HWn;
        float* ob = out + (size_t)b * On * HWn;
#pragma unroll
        for (int nt = 0; nt < 8; nt++) {
            int o = col0 + wn * 64 + nt * 8 + tq * 2;
            float b0v = __ldg(bias + o);
            float b1v = __ldg(bias + o + 1);
            float* p0 = ob + (size_t)o * HWn + pix;
            float* p1 = ob + (size_t)(o + 1) * HWn + pix;
            p0[0] = acc[mt][nt][0] + b0v;
            p1[0] = acc[mt][nt][1] + b1v;
            p0[8] = acc[mt][nt][2] + b0v;
            p1[8] = acc[mt][nt][3] + b1v;
        }
    }
}

// ---------------------------------------------------------------------------
// Launch
// ---------------------------------------------------------------------------
extern "C" void kernel_launch(void* const* d_in, const int* in_sizes, int n_in,
                              void* d_out, int out_size)
{
    const float* x        = (const float*)d_in[0];
    const float* offset_w = (const float*)d_in[1];
    const float* offset_b = (const float*)d_in[2];
    const float* mask_w   = (const float*)d_in[3];
    const float* mask_b   = (const float*)d_in[4];
    const float* weight   = (const float*)d_in[5];
    const float* bias     = (const float*)d_in[6];
    float* out = (float*)d_out;

    cudaFuncSetAttribute(offmask_kernel,
                         cudaFuncAttributeMaxDynamicSharedMemorySize, WS1_BYTES);
    cudaFuncSetAttribute(gemm_kernel,
                         cudaFuncAttributeMaxDynamicSharedMemorySize, GEMM_SMEM);

    prep_w<<<(On * CKn + 255) / 256, 256>>>(weight);
    offmask_kernel<<<(Bn * HWn) / 256, 256, WS1_BYTES>>>(
        x, offset_w, offset_b, mask_w, mask_b);
    gather_kernel<<<Bn * Hn * 3, 256>>>(x);
    dim3 grid(MTOT / BM, On / BN);
    gemm_kernel<<<grid, 256, GEMM_SMEM>>>(bias, out);
}

// round 10
// speedup vs baseline: 4.1271x; 1.0674x over previous
#include <cuda_runtime.h>
#include <cuda_bf16.h>
#include <math.h>
#include <cstdint>

// Problem constants
static constexpr int Bn = 8;
static constexpr int Cn = 128;
static constexpr int On = 256;
static constexpr int Hn = 96;
static constexpr int Wn = 96;
static constexpr int HWn = Hn * Wn;        // 9216
static constexpr int KKn = 9;
static constexpr int CKn = Cn * KKn;       // 1152
static constexpr int NCH = 27;
static constexpr int KP  = 2 * CKn;        // 2304: A stored as [Ah | Al]
static constexpr int KP3 = 3 * CKn;        // 3456: logical GEMM K
static constexpr int MTOT = Bn * HWn;      // 73728
static constexpr int BM = 128, BN = 128, BK = 64;
static constexpr int NST = KP3 / BK;       // 54

// Scratch
__device__ float         g_offmask[Bn * NCH * HWn];
__device__ __nv_bfloat16 g_A2[(size_t)MTOT * KP];     // [Ah | Al] per row
__device__ __nv_bfloat16 g_B2[(size_t)On * KP3];      // [Bh | Bh | Bl] per row

// ---------------------------------------------------------------------------
// PTX helpers
// ---------------------------------------------------------------------------
__device__ __forceinline__ uint32_t smem_u32(const void* p) {
    uint32_t a;
    asm("{ .reg .u64 t; cvta.to.shared.u64 t, %1; cvt.u32.u64 %0, t; }"
        : "=r"(a) : "l"(p));
    return a;
}
__device__ __forceinline__ void cp_async16(uint32_t dst, const void* src) {
    asm volatile("cp.async.cg.shared.global [%0], [%1], 16;"
                 :: "r"(dst), "l"(src) : "memory");
}
#define CP_COMMIT() asm volatile("cp.async.commit_group;" ::: "memory")
#define CP_WAIT1()  asm volatile("cp.async.wait_group 1;" ::: "memory")

__device__ __forceinline__ void ldmx4(uint32_t& r0, uint32_t& r1,
                                      uint32_t& r2, uint32_t& r3, uint32_t addr) {
    asm volatile("ldmatrix.sync.aligned.m8n8.x4.shared.b16 {%0,%1,%2,%3}, [%4];"
                 : "=r"(r0), "=r"(r1), "=r"(r2), "=r"(r3) : "r"(addr));
}
__device__ __forceinline__ void mma_bf16(float* c, const uint32_t* a,
                                         uint32_t b0, uint32_t b1) {
    asm volatile(
        "mma.sync.aligned.m16n8k16.row.col.f32.bf16.bf16.f32 "
        "{%0,%1,%2,%3}, {%4,%5,%6,%7}, {%8,%9}, {%0,%1,%2,%3};"
        : "+f"(c[0]), "+f"(c[1]), "+f"(c[2]), "+f"(c[3])
        : "r"(a[0]), "r"(a[1]), "r"(a[2]), "r"(a[3]), "r"(b0), "r"(b1));
}

// ---------------------------------------------------------------------------
// Kernel: weight -> bf16 3-term layout [Bh | Bh | Bl], [O][KP3]
// ---------------------------------------------------------------------------
__global__ void prep_w(const float* __restrict__ w) {
    int i = blockIdx.x * 256 + threadIdx.x;
    if (i < On * CKn) {
        int o = i / CKn, ck = i % CKn;
        float v = w[i];
        __nv_bfloat16 hi = __float2bfloat16(v);
        __nv_bfloat16 lo = __float2bfloat16(v - __bfloat162float(hi));
        __nv_bfloat16* row = g_B2 + (size_t)o * KP3;
        row[ck]           = hi;
        row[CKn + ck]     = hi;
        row[2 * CKn + ck] = lo;
    }
}

// ---------------------------------------------------------------------------
// Kernel: offset + mask 3x3 conv (27 channels), fp32 direct.
// v2: each thread computes 2 pixels (batch b and b+4, same spatial pos) --
// identical tap geometry, one smem weight read feeds both accumulators.
// ---------------------------------------------------------------------------
static constexpr int WS1_FLOATS = NCH * Cn * 12;
static constexpr int WS1_BYTES  = WS1_FLOATS * 4;

__global__ void __launch_bounds__(256) offmask_kernel(
    const float* __restrict__ x,
    const float* __restrict__ off_w, const float* __restrict__ off_b,
    const float* __restrict__ msk_w, const float* __restrict__ msk_b)
{
    extern __shared__ float ws[];
    int tid = threadIdx.x;
    for (int i = tid; i < WS1_FLOATS; i += 256) {
        int tap = i % 12;
        int c   = (i / 12) % Cn;
        int ch  = i / (12 * Cn);
        float v = 0.0f;
        if (tap < 9)
            v = (ch < 18) ? off_w[(ch * Cn + c) * 9 + tap]
                          : msk_w[((ch - 18) * Cn + c) * 9 + tap];
        ws[i] = v;
    }
    __syncthreads();

    int g = blockIdx.x * 256 + tid;       // 0 .. MTOT/2-1 (grid 144)
    int b   = g / HWn;                    // 0..3
    int pix = g % HWn;
    int oh  = pix / Wn;
    int owp = pix % Wn;

    int  offs[9];
    bool valt[9];
#pragma unroll
    for (int kh = 0; kh < 3; kh++)
#pragma unroll
        for (int kw = 0; kw < 3; kw++) {
            int y  = oh - 1 + kh;
            int xx = owp - 1 + kw;
            bool v = (y >= 0 && y < Hn && xx >= 0 && xx < Wn);
            valt[kh * 3 + kw] = v;
            offs[kh * 3 + kw] = v ? (y * Wn + xx) : 0;
        }

    float acc0[NCH], acc1[NCH];
#pragma unroll
    for (int ch = 0; ch < NCH; ch++) {
        float bv = (ch < 18) ? off_b[ch] : msk_b[ch - 18];
        acc0[ch] = bv;
        acc1[ch] = bv;
    }

    const float* xb0 = x + (size_t)b * Cn * HWn;
    const float* xb1 = xb0 + (size_t)4 * Cn * HWn;
    for (int c = 0; c < Cn; c++) {
        float xv0[9], xv1[9];
        const float* xc0 = xb0 + c * HWn;
        const float* xc1 = xb1 + c * HWn;
#pragma unroll
        for (int j = 0; j < 9; j++) {
            xv0[j] = valt[j] ? xc0[offs[j]] : 0.0f;
            xv1[j] = valt[j] ? xc1[offs[j]] : 0.0f;
        }
#pragma unroll
        for (int ch = 0; ch < NCH; ch++) {
            const float4* wp = (const float4*)&ws[(ch * Cn + c) * 12];
            float4 wa = wp[0];
            float4 wb = wp[1];
            float  w8 = ws[(ch * Cn + c) * 12 + 8];
            acc0[ch] += xv0[0] * wa.x + xv0[1] * wa.y + xv0[2] * wa.z + xv0[3] * wa.w
                      + xv0[4] * wb.x + xv0[5] * wb.y + xv0[6] * wb.z + xv0[7] * wb.w
                      + xv0[8] * w8;
            acc1[ch] += xv1[0] * wa.x + xv1[1] * wa.y + xv1[2] * wa.z + xv1[3] * wa.w
                      + xv1[4] * wb.x + xv1[5] * wb.y + xv1[6] * wb.z + xv1[7] * wb.w
                      + xv1[8] * w8;
        }
    }

    float* dst0 = g_offmask + (size_t)b * NCH * HWn + pix;
    float* dst1 = dst0 + (size_t)4 * NCH * HWn;
#pragma unroll
    for (int ch = 0; ch < NCH; ch++) {
        float v0 = acc0[ch], v1 = acc1[ch];
        if (ch >= 18) {
            v0 = 1.0f / (1.0f + expf(-v0));
            v1 = 1.0f / (1.0f + expf(-v1));
        }
        dst0[ch * HWn] = v0;
        dst1[ch * HWn] = v1;
    }
}

// ---------------------------------------------------------------------------
// Kernel: bilinear gather -> A2 [M][KP] bf16 [Ah | Al], mask folded in.
// v3: meta packed as float4/int4 -> 2x LDS.128 per sample.
// ---------------------------------------------------------------------------
__global__ void __launch_bounds__(256) gather_kernel(const float* __restrict__ x)
{
    __shared__ float4 mw4[288];
    __shared__ int4   mo4[288];

    int blk = blockIdx.x;
    int b   = blk / (Hn * 3);
    int r   = blk % (Hn * 3);
    int oh  = r / 3;
    int ow0 = (r % 3) * 32;
    int tid = threadIdx.x;
    int wid = tid >> 5;
    int lane = tid & 31;

    const float* om = g_offmask + (size_t)b * NCH * HWn;
    for (int i = tid; i < 288; i += 256) {
        int p = i / KKn;
        int k = i % KKn;
        int pix = oh * Wn + ow0 + p;
        float offy = om[(2 * k) * HWn + pix];
        float offx = om[(2 * k + 1) * HWn + pix];
        float m    = om[(18 + k) * HWn + pix];
        float py = (float)(oh - 1 + k / 3) + offy;
        float px = (float)(ow0 + p - 1 + k % 3) + offx;
        float y0f = floorf(py), x0f = floorf(px);
        int y0 = (int)y0f, x0 = (int)x0f;
        int y1 = y0 + 1,  x1 = x0 + 1;
        float wy1 = py - y0f, wy0 = 1.0f - wy1;
        float wx1 = px - x0f, wx0 = 1.0f - wx1;
        bool vy0 = (y0 >= 0 && y0 < Hn), vy1 = (y1 >= 0 && y1 < Hn);
        bool vx0 = (x0 >= 0 && x0 < Wn), vx1 = (x1 >= 0 && x1 < Wn);
        int cy0 = min(max(y0, 0), Hn - 1), cy1 = min(max(y1, 0), Hn - 1);
        int cx0 = min(max(x0, 0), Wn - 1), cx1 = min(max(x1, 0), Wn - 1);
        mw4[i] = make_float4(
            wy0 * wx0 * m * ((vy0 && vx0) ? 1.0f : 0.0f),
            wy0 * wx1 * m * ((vy0 && vx1) ? 1.0f : 0.0f),
            wy1 * wx0 * m * ((vy1 && vx0) ? 1.0f : 0.0f),
            wy1 * wx1 * m * ((vy1 && vx1) ? 1.0f : 0.0f));
        mo4[i] = make_int4(cy0 * Wn + cx0, cy0 * Wn + cx1,
                           cy1 * Wn + cx0, cy1 * Wn + cx1);
    }
    __syncthreads();

    const float* xb = x + (size_t)b * Cn * HWn;
    size_t arow0 = ((size_t)b * HWn + oh * Wn + ow0) * KP;

#pragma unroll
    for (int pp = 0; pp < 4; pp++) {
        int p = pp * 8 + wid;
        __nv_bfloat16* dst = g_A2 + arow0 + (size_t)p * KP;
        int mbase = p * 9;
#pragma unroll 4
        for (int j = 0; j < 36; j++) {
            int ck = j * 32 + lane;
            int c = ck / 9, k = ck - c * 9;
            int mi = mbase + k;
            const float* xc = xb + c * HWn;
            float4 w = mw4[mi];
            int4   o = mo4[mi];
            float v = w.x * xc[o.x] + w.y * xc[o.y]
                    + w.z * xc[o.z] + w.w * xc[o.w];
            __nv_bfloat16 hi = __float2bfloat16(v);
            __nv_bfloat16 lo = __float2bfloat16(v - __bfloat162float(hi));
            dst[ck]       = hi;
            dst[CKn + ck] = lo;
        }
    }
}

// ---------------------------------------------------------------------------
// Kernel: bf16 HMMA GEMM, CTA 128x128, BK=64, 3-stage cp.async pipeline.
// K'=3456 (3-term split, A segment 3 aliases 1). Pitch 144B (conflict-free).
// Grid (N=2, M=576): N-tiles of the same M-row adjacent -> A L2 reuse.
// ---------------------------------------------------------------------------
static constexpr int PITCH  = 144;                // bytes per smem row (64 bf16 + pad)
static constexpr int ABYTES = BM * PITCH;         // 18432
static constexpr int BUFB   = 2 * ABYTES;         // A+B per stage: 36864
static constexpr int GEMM_SMEM = 3 * BUFB;        // 110592

__global__ void __launch_bounds__(256, 2) gemm_kernel(
    const float* __restrict__ bias, float* __restrict__ out)
{
    extern __shared__ __align__(16) char sm[];
    uint32_t sb = smem_u32(sm);
    int tid  = threadIdx.x;
    int wid  = tid >> 5;
    int lane = tid & 31;
    int wm = wid & 3;
    int wn = wid >> 2;

    int row0 = blockIdx.y * BM;     // M tile
    int col0 = blockIdx.x * BN;     // N tile

    auto load_stage = [&](int s) {
        int kc  = s * BK;
        int akc = (kc < KP) ? kc : kc - KP;   // A third segment re-reads Ah
        uint32_t dst = sb + (s % 3) * BUFB;
#pragma unroll
        for (int i = 0; i < 4; i++) {
            int ch = tid + i * 256;           // 0..1023
            int r = ch >> 3, u = ch & 7;
            cp_async16(dst + r * PITCH + u * 16,
                       g_A2 + (size_t)(row0 + r) * KP + akc + u * 8);
        }
        uint32_t dstb = dst + ABYTES;
#pragma unroll
        for (int i = 0; i < 4; i++) {
            int ch = tid + i * 256;
            int r = ch >> 3, u = ch & 7;
            cp_async16(dstb + r * PITCH + u * 16,
                       g_B2 + (size_t)(col0 + r) * KP3 + kc + u * 8);
        }
        CP_COMMIT();
    };

    float acc[2][8][4];
#pragma unroll
    for (int mt = 0; mt < 2; mt++)
#pragma unroll
        for (int nt = 0; nt < 8; nt++)
#pragma unroll
            for (int e = 0; e < 4; e++) acc[mt][nt][e] = 0.0f;

    load_stage(0);
    load_stage(1);

    int lrow = lane & 15;
    int lcol = (lane >> 4) * 8;

    for (int s = 0; s < NST; s++) {
        CP_WAIT1();              // stage s complete (s+1 may fly)
        __syncthreads();         // everyone finished reading buf (s-1)%3
        if (s + 2 < NST) load_stage(s + 2);   // overwrites buf (s-1)%3

        uint32_t bufA = sb + (s % 3) * BUFB;
        uint32_t bufB = bufA + ABYTES;

#pragma unroll
        for (int kk = 0; kk < 4; kk++) {
            int colb = (kk * 16 + lcol) * 2;
            uint32_t a[2][4];
#pragma unroll
            for (int mt = 0; mt < 2; mt++) {
                int row = wm * 32 + mt * 16 + lrow;
                ldmx4(a[mt][0], a[mt][1], a[mt][2], a[mt][3],
                      bufA + row * PITCH + colb);
            }
#pragma unroll
            for (int ntp = 0; ntp < 4; ntp++) {
                int row = wn * 64 + ntp * 16 + lrow;
                uint32_t b0, b1, b2, b3;
                ldmx4(b0, b1, b2, b3, bufB + row * PITCH + colb);
#pragma unroll
                for (int mt = 0; mt < 2; mt++) {
                    mma_bf16(acc[mt][2 * ntp],     a[mt], b0, b2);
                    mma_bf16(acc[mt][2 * ntp + 1], a[mt], b1, b3);
                }
            }
        }
    }

    // Epilogue (validated mapping)
    int quad = lane >> 2;
    int tq   = lane & 3;
#pragma unroll
    for (int mt = 0; mt < 2; mt++) {
        int m = row0 + wm * 32 + mt * 16 + quad;
        int b   = m / HWn;
        int pix = m % HWn;
        float* ob = out + (size_t)b * On * HWn;
#pragma unroll
        for (int nt = 0; nt < 8; nt++) {
            int o = col0 + wn * 64 + nt * 8 + tq * 2;
            float b0v = __ldg(bias + o);
            float b1v = __ldg(bias + o + 1);
            float* p0 = ob + (size_t)o * HWn + pix;
            float* p1 = ob + (size_t)(o + 1) * HWn + pix;
            p0[0] = acc[mt][nt][0] + b0v;
            p1[0] = acc[mt][nt][1] + b1v;
            p0[8] = acc[mt][nt][2] + b0v;
            p1[8] = acc[mt][nt][3] + b1v;
        }
    }
}

// ---------------------------------------------------------------------------
// Launch
// ---------------------------------------------------------------------------
extern "C" void kernel_launch(void* const* d_in, const int* in_sizes, int n_in,
                              void* d_out, int out_size)
{
    const float* x        = (const float*)d_in[0];
    const float* offset_w = (const float*)d_in[1];
    const float* offset_b = (const float*)d_in[2];
    const float* mask_w   = (const float*)d_in[3];
    const float* mask_b   = (const float*)d_in[4];
    const float* weight   = (const float*)d_in[5];
    const float* bias     = (const float*)d_in[6];
    float* out = (float*)d_out;

    cudaFuncSetAttribute(offmask_kernel,
                         cudaFuncAttributeMaxDynamicSharedMemorySize, WS1_BYTES);
    cudaFuncSetAttribute(gemm_kernel,
                         cudaFuncAttributeMaxDynamicSharedMemorySize, GEMM_SMEM);

    prep_w<<<(On * CKn + 255) / 256, 256>>>(weight);
    offmask_kernel<<<(Bn * HWn / 2) / 256, 256, WS1_BYTES>>>(
        x, offset_w, offset_b, mask_w, mask_b);
    gather_kernel<<<Bn * Hn * 3, 256>>>(x);
    dim3 grid(On / BN, MTOT / BM);   // N-major -> A tile L2 reuse
    gemm_kernel<<<grid, 256, GEMM_SMEM>>>(bias, out);
}